// round 1
// baseline (speedup 1.0000x reference)
#include <cuda_runtime.h>
#include <cuda_bf16.h>

// Problem shapes (fixed)
#define BN 16
#define FN 4096
#define MN 512
#define DN 256
#define VEN 64
#define HN 512
#define OUTN 8
#define INW (VEN + DN)   // 320

// Device scratch (no allocations allowed)
__device__ __align__(16) float g_WcT[OUTN * INW];   // transposed combined weight: [k][i], i<64 emb, i>=64 feat
__device__ __align__(16) float g_bc[OUTN];          // combined bias
__device__ __align__(16) float g_sum[BN * MN * OUTN]; // segment sums of projected frames
__device__ __align__(16) float g_cnt[BN * MN];        // segment counts

// ---------------------------------------------------------------------------
// Kernel A: zero accumulators + fold Wc = W_mora @ W_post, bc = b_mora@W_post + b_post
// One warp per row i of W_mora (320 warps) + 1 warp for the bias.
// ---------------------------------------------------------------------------
__global__ __launch_bounds__(256) void init_kernel(
    const float* __restrict__ W_mora,   // [320, 512]
    const float* __restrict__ b_mora,   // [512]
    const float* __restrict__ W_post,   // [512, 8]
    const float* __restrict__ b_post)   // [8]
{
    const int t = blockIdx.x * blockDim.x + threadIdx.x;
    const int nthr = gridDim.x * blockDim.x;

    // zero accumulators (grid-stride)
    for (int i = t; i < BN * MN * OUTN; i += nthr) g_sum[i] = 0.0f;
    for (int i = t; i < BN * MN; i += nthr) g_cnt[i] = 0.0f;

    const int warp = t >> 5;
    const int lane = t & 31;

    if (warp < INW) {
        // Wc[i][k] = sum_h W_mora[i][h] * W_post[h][k]
        const int i = warp;
        const float* wr = W_mora + i * HN;
        float s[OUTN];
#pragma unroll
        for (int k = 0; k < OUTN; k++) s[k] = 0.0f;
        for (int h = lane; h < HN; h += 32) {
            float a = wr[h];
            float4 p0 = *(const float4*)(W_post + h * OUTN);
            float4 p1 = *(const float4*)(W_post + h * OUTN + 4);
            s[0] += a * p0.x; s[1] += a * p0.y; s[2] += a * p0.z; s[3] += a * p0.w;
            s[4] += a * p1.x; s[5] += a * p1.y; s[6] += a * p1.z; s[7] += a * p1.w;
        }
#pragma unroll
        for (int off = 16; off; off >>= 1) {
#pragma unroll
            for (int k = 0; k < OUTN; k++)
                s[k] += __shfl_xor_sync(0xFFFFFFFFu, s[k], off);
        }
        if (lane == 0) {
#pragma unroll
            for (int k = 0; k < OUTN; k++) g_WcT[k * INW + i] = s[k];
        }
    } else if (warp == INW) {
        // bc[k] = b_post[k] + sum_h b_mora[h] * W_post[h][k]
        float s[OUTN];
#pragma unroll
        for (int k = 0; k < OUTN; k++) s[k] = 0.0f;
        for (int h = lane; h < HN; h += 32) {
            float a = b_mora[h];
            float4 p0 = *(const float4*)(W_post + h * OUTN);
            float4 p1 = *(const float4*)(W_post + h * OUTN + 4);
            s[0] += a * p0.x; s[1] += a * p0.y; s[2] += a * p0.z; s[3] += a * p0.w;
            s[4] += a * p1.x; s[5] += a * p1.y; s[6] += a * p1.z; s[7] += a * p1.w;
        }
#pragma unroll
        for (int off = 16; off; off >>= 1) {
#pragma unroll
            for (int k = 0; k < OUTN; k++)
                s[k] += __shfl_xor_sync(0xFFFFFFFFu, s[k], off);
        }
        if (lane == 0) {
#pragma unroll
            for (int k = 0; k < OUTN; k++) g_bc[k] = s[k] + b_post[k];
        }
    }
}

// ---------------------------------------------------------------------------
// Kernel B: project each frame to 8 dims with Wc_feat (rows 64..319 of Wc),
// segment-scatter (atomicAdd) into g_sum / g_cnt.
// One warp per frame, grid-stride over frames; weights held in registers.
// Lane l owns feature dims {4l..4l+3} and {128+4l..128+4l+3}.
// ---------------------------------------------------------------------------
__global__ __launch_bounds__(256) void proj_kernel(
    const float* __restrict__ features,   // [B, F, D]
    const int* __restrict__ mora_index)   // [B, F]
{
    const int lane = threadIdx.x & 31;
    const int warp = (blockIdx.x * blockDim.x + threadIdx.x) >> 5;
    const int totalWarps = (gridDim.x * blockDim.x) >> 5;

    // load this lane's weight slice once (hot in L1/L2 across warps)
    float4 w0[OUTN], w1[OUTN];
#pragma unroll
    for (int k = 0; k < OUTN; k++) {
        w0[k] = *(const float4*)(g_WcT + k * INW + VEN + 4 * lane);
        w1[k] = *(const float4*)(g_WcT + k * INW + VEN + 128 + 4 * lane);
    }

    for (int g = warp; g < BN * FN; g += totalWarps) {
        const float* fr = features + (size_t)g * DN;
        float4 x0 = *(const float4*)(fr + 4 * lane);
        float4 x1 = *(const float4*)(fr + 128 + 4 * lane);

        float acc[OUTN];
#pragma unroll
        for (int k = 0; k < OUTN; k++) {
            acc[k] = x0.x * w0[k].x + x0.y * w0[k].y + x0.z * w0[k].z + x0.w * w0[k].w
                   + x1.x * w1[k].x + x1.y * w1[k].y + x1.z * w1[k].z + x1.w * w1[k].w;
        }
#pragma unroll
        for (int off = 16; off; off >>= 1) {
#pragma unroll
            for (int k = 0; k < OUTN; k++)
                acc[k] += __shfl_xor_sync(0xFFFFFFFFu, acc[k], off);
        }
        if (lane == 0) {
            int b = g >> 12;               // / FN
            int m = mora_index[g];
            float* dst = g_sum + (size_t)((b << 9) + m) * OUTN;  // * MN=512
#pragma unroll
            for (int k = 0; k < OUTN; k++) atomicAdd(dst + k, acc[k]);
            atomicAdd(g_cnt + (b << 9) + m, 1.0f);
        }
    }
}

// ---------------------------------------------------------------------------
// Kernel C: finalize per (b, m, k):
//   out = emb_table[vowel] . Wc_emb[:,k]  +  (cnt>0 ? sum[k]/cnt : 0)  +  bc[k]
// One thread per output element (B*M*8 = 65536 threads).
// ---------------------------------------------------------------------------
__global__ __launch_bounds__(256) void final_kernel(
    const int* __restrict__ vowels,       // [B, M]
    const float* __restrict__ emb_table,  // [V, VE]
    float* __restrict__ out)              // [B, M, 8]
{
    const int t = blockIdx.x * blockDim.x + threadIdx.x;
    if (t >= BN * MN * OUTN) return;
    const int k = t & 7;
    const int row = t >> 3;

    const int v = vowels[row];
    const float* e = emb_table + v * VEN;
    const float* w = g_WcT + k * INW;   // first 64 entries = emb part

    float s = g_bc[k];
#pragma unroll 8
    for (int j = 0; j < VEN; j++) s += e[j] * w[j];

    float cnt = g_cnt[row];
    if (cnt > 0.0f) s += g_sum[t] * (1.0f / cnt);
    out[t] = s;
}

// ---------------------------------------------------------------------------
// launch
// ---------------------------------------------------------------------------
extern "C" void kernel_launch(void* const* d_in, const int* in_sizes, int n_in,
                              void* d_out, int out_size)
{
    const int*   vowels     = (const int*)d_in[0];
    const float* features   = (const float*)d_in[1];
    const int*   mora_index = (const int*)d_in[2];
    const float* emb_table  = (const float*)d_in[3];
    const float* W_mora     = (const float*)d_in[4];
    const float* b_mora     = (const float*)d_in[5];
    // d_in[6] = W_frame, d_in[7] = b_frame: dead branch in reference, unused
    const float* W_post     = (const float*)d_in[8];
    const float* b_post     = (const float*)d_in[9];
    float* out = (float*)d_out;

    init_kernel<<<288, 256>>>(W_mora, b_mora, W_post, b_post);
    proj_kernel<<<1024, 256>>>(features, mora_index);
    final_kernel<<<(BN * MN * OUTN + 255) / 256, 256>>>(vowels, emb_table, out);
}